// round 13
// baseline (speedup 1.0000x reference)
#include <cuda_runtime.h>

#define BB 2
#define CC 20
#define DD 256
#define WW 448
#define HWp 200704      // 448*448
#define FH 28
#define FW 28
#define FHW 784
#define KTOP 25

// ---- scratch (device globals). Invariant: zero at launch entry; cleanup is
// distributed across k_main phase-B blocks + tail block, and g_psync resets
// itself inside k_pseudo. g_Wt/g_G/g_nrm are overwrite-before-read.
static __device__ float g_W   [BB*CC*FHW];
static __device__ float g_Wt  [BB*CC*FHW];
static __device__ int   g_cnt [BB*CC];
static __device__ int   g_psync;         // fan-in counter for k_pseudo tail
static __device__ int   g_sync1;         // k_main grid barrier
static __device__ int   g_sync2;         // k_main epilogue fan-in
static __device__ float g_fsm [BB*CC*DD];
static __device__ float g_G   [60*40];   // G[t][s]: t in {fc0(0-19), f0(20-39), proj(40-59)}, s in {f0(0-19), f1(20-39)}
static __device__ float g_nrm [3*CC];    // sumsq rows: 0:f0, 1:f1, 2:fc0

// ---- pseudo-label + bilinear-weight scatter; last block runs the (rare)
//      top-25 fallback for present classes with zero labeled pixels ----
__global__ __launch_bounds__(256) void k_pseudo(
    const float* __restrict__ cam, const float* __restrict__ label,
    const float* __restrict__ hig, const float* __restrict__ low,
    const float* __restrict__ bg)
{
    __shared__ int   s_np;
    __shared__ int   s_list[CC];
    __shared__ float s_W[CC*3*30];   // [c][row 0..2][col 0..29] unclamped tile
    __shared__ int   s_cnt[CC];

    int tid = threadIdx.x;
    int b    = blockIdx.x / 196;
    int pblk = blockIdx.x % 196;
    int P0   = pblk * 1024;
    int p    = P0 + tid * 4;

    for (int i = tid; i < CC*90; i += 256) s_W[i] = 0.f;
    if (tid < CC) s_cnt[tid] = 0;
    if (tid < 32) {
        float lv = (tid < CC) ? __ldg(&label[b*CC + tid]) : 0.f;
        unsigned m = __ballot_sync(0xffffffffu, lv > 0.5f);
        if (tid < CC && lv > 0.5f) {
            int pos = __popc(m & ((1u << tid) - 1u));
            s_list[pos] = tid;
        }
        if (tid == 0) s_np = __popc(m);
    }
    __syncthreads();

    int np = s_np;
    const float* base = cam + (size_t)b * CC * HWp;

    float t1[4], t2[4];
    #pragma unroll
    for (int e = 0; e < 4; e++) { t1[e] = -1e30f; t2[e] = -1e30f; }

    for (int k = 0; k < np; k++) {
        int c = s_list[k];
        float4 v = __ldg((const float4*)(base + (size_t)c * HWp + p));
        float tm;
        tm = fminf(t1[0], v.x); t2[0] = fmaxf(t2[0], tm); t1[0] = fmaxf(t1[0], v.x);
        tm = fminf(t1[1], v.y); t2[1] = fmaxf(t2[1], tm); t1[1] = fmaxf(t1[1], v.y);
        tm = fminf(t1[2], v.z); t2[2] = fmaxf(t2[2], tm); t1[2] = fmaxf(t1[2], v.z);
        tm = fminf(t1[3], v.w); t2[3] = fmaxf(t2[3], tm); t1[3] = fmaxf(t1[3], v.w);
    }
    float Hh = __ldg(hig), Ll = __ldg(low), Gg = __ldg(bg);

    int Y0 = P0 / WW;
    int r0 = (int)floorf(((float)Y0 + 0.5f) * 0.0625f - 0.5f);

    #pragma unroll
    for (int e = 0; e < 4; e++) {
        float a = t1[e], s = t2[e];
        if (np < CC) { a = fmaxf(a, 0.f); s = fmaxf(s, 0.f); }  // absent classes are zeros
        bool lab = !(a < Hh) && !(a < Ll) && !(a < Gg) && !((a - s < 0.3f) && (a > Hh));
        lab = lab && (np > 0);
        if (lab) {
            int c = s_list[0];
            if (np > 1) {
                int pp0 = p + e;
                for (int k = 0; k < np; k++) {
                    int cc2 = s_list[k];
                    if (__ldg(&base[(size_t)cc2 * HWp + pp0]) == a) { c = cc2; break; }
                }
            }
            atomicAdd(&s_cnt[c], 1);
            int pp = p + e;
            int y = pp / WW, x = pp - y * WW;
            float sy = ((float)y + 0.5f) * 0.0625f - 0.5f;   // exact (dyadic)
            float sx = ((float)x + 0.5f) * 0.0625f - 0.5f;
            float y0f = floorf(sy), x0f = floorf(sx);
            float fy = sy - y0f,   fx = sx - x0f;
            int rr  = (int)y0f - r0;        // 0..1 (taps rr, rr+1 in [0,2])
            int c0  = (int)x0f + 1;         // 0..28
            float* tp = &s_W[c*90 + rr*30 + c0];
            atomicAdd(&tp[0],  (1.f-fy)*(1.f-fx));
            atomicAdd(&tp[1],  (1.f-fy)*fx);
            atomicAdd(&tp[30], fy*(1.f-fx));
            atomicAdd(&tp[31], fy*fx);
        }
    }
    __syncthreads();

    if (tid < CC && s_cnt[tid] > 0) atomicAdd(&g_cnt[b*CC + tid], s_cnt[tid]);
    for (int i = tid; i < CC*90; i += 256) {
        float v = s_W[i];
        if (v != 0.f) {
            int c = i / 90, rem = i - c*90;
            int rr = rem / 30, col = rem - rr*30;
            int gy = min(max(r0 + rr, 0), FH-1);
            int gx = min(max(col - 1, 0), FW-1);
            atomicAdd(&g_W[(b*CC + c)*FHW + gy*FW + gx], v);
        }
    }

    // ---- fan-in tail: last block handles rare count==0 present classes ----
    __threadfence();
    __shared__ int s_last;
    if (tid == 0) s_last = (atomicAdd(&g_psync, 1) == BB*196 - 1) ? 1 : 0;
    __syncthreads();
    if (!s_last) return;
    __threadfence();

    int wid = tid >> 5, lane = tid & 31;
    __shared__ float s_wv[8];
    __shared__ int   s_wi[8];
    __shared__ int   s_bi;
    __shared__ int   s_top[KTOP];
    __shared__ float s_wt[FHW];

    for (int bc = 0; bc < BB*CC; bc++) {
        if (__ldg(&label[bc]) <= 0.5f) continue;
        if (g_cnt[bc] != 0) continue;

        // full-plane per-thread heaps
        const float4* cp = (const float4*)(cam + (size_t)bc * HWp);
        float vals[KTOP]; int idxs[KTOP];   // ascending: vals[24]=max
        #pragma unroll
        for (int k = 0; k < KTOP; k++) { vals[k] = -1e30f; idxs[k] = 0x7fffffff; }
        float vmin = -1e30f;
        for (int j = tid; j < HWp/4; j += 256) {
            float4 v = __ldg(&cp[j]);
            int pbase = j * 4;
            float vv[4] = { v.x, v.y, v.z, v.w };
            #pragma unroll
            for (int e = 0; e < 4; e++) {
                float x = vv[e];
                if (x > vmin) {
                    int k = 0;
                    while (k < KTOP-1 && x > vals[k+1]) { vals[k] = vals[k+1]; idxs[k] = idxs[k+1]; k++; }
                    vals[k] = x; idxs[k] = pbase + e;
                    vmin = vals[0];
                }
            }
        }
        // 25 rounds of block argmax (value desc, index asc tie-break)
        int ptr = KTOP - 1;
        for (int r = 0; r < KTOP; r++) {
            float v  = (ptr >= 0) ? vals[ptr] : -1e30f;
            int   ii = (ptr >= 0) ? idxs[ptr] : 0x7fffffff;
            float mv = v; int mi = ii;
            #pragma unroll
            for (int off = 16; off > 0; off >>= 1) {
                float ov = __shfl_down_sync(0xffffffffu, mv, off);
                int   oi = __shfl_down_sync(0xffffffffu, mi, off);
                if (ov > mv || (ov == mv && oi < mi)) { mv = ov; mi = oi; }
            }
            if (lane == 0) { s_wv[wid] = mv; s_wi[wid] = mi; }
            __syncthreads();
            if (tid == 0) {
                float bv = s_wv[0]; int bi = s_wi[0];
                #pragma unroll
                for (int w = 1; w < 8; w++) {
                    if (s_wv[w] > bv || (s_wv[w] == bv && s_wi[w] < bi)) { bv = s_wv[w]; bi = s_wi[w]; }
                }
                s_bi = bi;
                s_top[r] = bi;
            }
            __syncthreads();
            if (ptr >= 0 && idxs[ptr] == s_bi) ptr--;
        }
        // taps -> g_Wt[bc]
        for (int i = tid; i < FHW; i += 256) s_wt[i] = 0.f;
        __syncthreads();
        if (tid == 0) {
            for (int r = 0; r < KTOP; r++) {
                int pp = s_top[r];
                int y = pp / WW, x = pp - y * WW;
                float sy = ((float)y + 0.5f) * 0.0625f - 0.5f;
                float sx = ((float)x + 0.5f) * 0.0625f - 0.5f;
                float y0f = floorf(sy), x0f = floorf(sx);
                float fy = sy - y0f,   fx = sx - x0f;
                int y0 = (int)y0f, x0 = (int)x0f;
                int ya = min(max(y0, 0), FH-1),   yb = min(max(y0+1, 0), FH-1);
                int xa = min(max(x0, 0), FW-1),   xb = min(max(x0+1, 0), FW-1);
                s_wt[ya*FW + xa] += (1.f-fy)*(1.f-fx);
                s_wt[ya*FW + xb] += (1.f-fy)*fx;
                s_wt[yb*FW + xa] += fy*(1.f-fx);
                s_wt[yb*FW + xb] += fy*fx;
            }
        }
        __syncthreads();
        for (int i = tid; i < FHW; i += 256) g_Wt[bc*FHW + i] = s_wt[i];
        __syncthreads();
    }
    if (tid == 0) g_psync = 0;
}

// ---- main: fsm -> grid barrier -> dots/norms/cleanup -> fan-in epilogue ----
// grid 60 x 256 (all blocks co-resident: 60 < 148 SMs => spin barrier safe).
// G mapping (t-major, stride 41 in shared): M0[c][j]=G[j][c]  M1[c][j]=G[j][20+c]
// M2[c][j]=G[20+j][20+c]  M3[c][j]=G[40+j][c]  M4[c][j]=G[40+j][20+c]
__global__ __launch_bounds__(256) void k_main(
    const float* __restrict__ fmap, const float* __restrict__ label,
    const float* __restrict__ fc0, const float* __restrict__ proj,
    float* __restrict__ out)
{
    int t = blockIdx.x;
    int tid = threadIdx.x, wid = tid >> 5, lane = tid & 31;

    // ================= Phase A: fsm (56 row-tasks) =================
    if (t < BB*FH) {
        __shared__ int    s_np, s_nact;
        __shared__ int    s_list[CC];
        __shared__ int    s_act[CC];
        __shared__ int    s_nz[CC];
        __shared__ int    s_cnti[CC];
        __shared__ float  s_inv[CC];
        __shared__ float4 s_cw[CC][7];

        int b = t / FH, row = t % FH;
        int d = tid;
        const float4* fr = (const float4*)(fmap + ((size_t)(b*DD + d)) * FHW + row*FW);
        float4 f[7];
        #pragma unroll
        for (int i = 0; i < 7; i++) f[i] = __ldg(&fr[i]);

        if (tid < 32) {
            float lv = (tid < CC) ? __ldg(&label[b*CC + tid]) : 0.f;
            unsigned m = __ballot_sync(0xffffffffu, lv > 0.5f);
            if (tid < CC && lv > 0.5f) s_list[__popc(m & ((1u << tid) - 1u))] = tid;
            if (tid == 0) s_np = __popc(m);
        }
        if (tid < CC) s_nz[tid] = 0;
        __syncthreads();
        int np = s_np;

        if (tid < np) {
            int bc = b*CC + s_list[tid];
            int cnt = g_cnt[bc];
            s_cnti[tid] = cnt;
            s_inv[tid]  = (cnt > 0) ? (1.f / (float)cnt) : 0.04f;
        }
        __syncthreads();

        for (int idx = tid; idx < np*7; idx += 256) {
            int k = idx / 7, q = idx - k*7;
            int bc = b*CC + s_list[k];
            const float4* src = (s_cnti[k] > 0)
                ? (const float4*)(g_W  + bc*FHW + row*FW)
                : (const float4*)(g_Wt + bc*FHW + row*FW);
            float4 v = src[q];
            float inv = s_inv[k];
            v.x *= inv; v.y *= inv; v.z *= inv; v.w *= inv;
            s_cw[k][q] = v;
            if (v.x != 0.f || v.y != 0.f || v.z != 0.f || v.w != 0.f) s_nz[k] = 1;
        }
        __syncthreads();

        if (tid < 32) {
            bool a = (tid < np) && s_nz[tid];
            unsigned m = __ballot_sync(0xffffffffu, a);
            if (a) s_act[__popc(m & ((1u << tid) - 1u))] = tid;
            if (tid == 0) s_nact = __popc(m);
        }
        __syncthreads();
        int nact = s_nact;

        for (int a = 0; a < nact; a++) {
            int k = s_act[a];
            int c = s_list[k];
            float a0 = 0.f, a1 = 0.f, a2 = 0.f, a3 = 0.f;
            #pragma unroll
            for (int i = 0; i < 7; i++) {
                float4 w = s_cw[k][i];
                a0 = fmaf(f[i].x, w.x, a0);
                a1 = fmaf(f[i].y, w.y, a1);
                a2 = fmaf(f[i].z, w.z, a2);
                a3 = fmaf(f[i].w, w.w, a3);
            }
            atomicAdd(&g_fsm[(b*CC + c)*DD + d], (a0 + a1) + (a2 + a3));
        }
    }

    // ================= Grid spin barrier (60 co-resident blocks) =========
    __threadfence();
    __syncthreads();
    if (tid == 0) {
        atomicAdd(&g_sync1, 1);
        while (atomicAdd(&g_sync1, 0) < 60) __nanosleep(64);
    }
    __syncthreads();
    __threadfence();

    // ================= Phase B: dots + norms + distributed cleanup ========
    {
        int type = t / 20, row = t % 20;
        const float* tp = (type == 0) ? (fc0 + row*DD)
                        : (type == 1) ? (g_fsm + row*DD)
                                      : (proj + row*DD);
        const float4* t4 = (const float4*)tp;
        float4 ta = __ldg(&t4[lane*2]);
        float4 tb = __ldg(&t4[lane*2 + 1]);
        #pragma unroll
        for (int i = 0; i < 5; i++) {
            int s = wid*5 + i;
            const float4* s4 = (const float4*)(g_fsm + s*DD);
            float4 sa = __ldg(&s4[lane*2]);
            float4 sb = __ldg(&s4[lane*2 + 1]);
            float d = sa.x*ta.x + sa.y*ta.y + sa.z*ta.z + sa.w*ta.w
                    + sb.x*tb.x + sb.y*tb.y + sb.z*tb.z + sb.w*tb.w;
            #pragma unroll
            for (int o = 16; o > 0; o >>= 1) d += __shfl_xor_sync(0xffffffffu, d, o);
            if (lane == 0) g_G[t*40 + s] = d;
        }
        // norms: type0 -> fc0 row (slot 40+row); type1 -> f0 row (slot row);
        //        type2 -> f1 row 20+row (slot 20+row, extra load)
        if (wid == 0) {
            float4 ua = ta, ub = tb;
            int slot;
            if (type == 0)      slot = 40 + row;
            else if (type == 1) slot = row;
            else {
                const float4* r4 = (const float4*)(g_fsm + (CC + row)*DD);
                ua = __ldg(&r4[lane*2]);
                ub = __ldg(&r4[lane*2 + 1]);
                slot = 20 + row;
            }
            float ss = ua.x*ua.x + ua.y*ua.y + ua.z*ua.z + ua.w*ua.w
                     + ub.x*ub.x + ub.y*ub.y + ub.z*ub.z + ub.w*ub.w;
            #pragma unroll
            for (int o = 16; o > 0; o >>= 1) ss += __shfl_xor_sync(0xffffffffu, ss, o);
            if (lane == 0) g_nrm[slot] = ss;
        }
        // distributed cleanup (g_W/g_cnt no longer read this launch)
        for (int i = t*256 + tid; i < BB*CC*FHW; i += 60*256) g_W[i] = 0.f;
        if (t == 0 && tid < BB*CC) g_cnt[tid] = 0;
    }

    // ================= Fan-in: last block runs the epilogue ==============
    __threadfence();
    __shared__ int s_last;
    if (tid == 0) s_last = (atomicAdd(&g_sync2, 1) == 59) ? 1 : 0;
    __syncthreads();
    if (!s_last) return;
    __threadfence();

    __shared__ float s_G[60*41];
    __shared__ float s_n[3][CC];
    __shared__ float s_invf0[CC], s_invf1[CC], s_invc0[CC], s_invc1[CC];
    __shared__ float s_rowsum[CC], s_term[CC];
    __shared__ int   s_q[CC], s_q1[CC];
    __shared__ float s_acc[2];

    for (int i = tid; i < 60*40; i += 256) {
        int tt2 = i / 40, s = i - tt2*40;
        s_G[tt2*41 + s] = __ldcg(&g_G[i]);
    }
    if (tid < 60) s_n[tid/CC][tid%CC] = __ldcg(&g_nrm[tid]);
    if (tid == 0) { s_acc[0] = 0.f; s_acc[1] = 0.f; }
    __syncthreads();

    if (tid < CC) {
        s_invf0[tid] = 1.f / fmaxf(sqrtf(s_n[0][tid]), 1e-12f);
        s_invf1[tid] = 1.f / fmaxf(sqrtf(s_n[1][tid]), 1e-12f);
        s_invc0[tid] = 1.f / fmaxf(sqrtf(s_n[2][tid]), 1e-12f);
    }
    __syncthreads();

    // ---- T0: batch-0 epilogue (8 warps, c strided) ----
    for (int c = wid; c < CC; c += 8) {
        int j = lane;
        bool pres = __ldg(&label[c]) > 0.5f;
        float v = 1e-5f;
        if (j < CC) {
            v = fabsf(s_G[j*41 + c] * s_invf0[c] * s_invc0[j]);
            v = fminf(fmaxf(v, 1e-5f), 1.f - 1e-5f);
        }
        float lt = 0.f, ov = -1e30f;
        if (j < CC) {
            lt = (j == c) ? (pres ? logf(v) : log1pf(-v)) : log1pf(-v);
            ov = (j == c) ? -1e30f : v;
        }
        float rs = lt, om = ov;
        #pragma unroll
        for (int o = 16; o > 0; o >>= 1) {
            rs += __shfl_xor_sync(0xffffffffu, rs, o);
            om  = fmaxf(om, __shfl_xor_sync(0xffffffffu, om, o));
        }
        if (lane == 0) { s_rowsum[c] = rs; s_q[c] = (pres && om < 0.6f) ? 1 : 0; }

        float x = (j < CC) ? s_G[(40+j)*41 + c] : -3.4e38f;
        float m = x;
        #pragma unroll
        for (int o = 16; o > 0; o >>= 1) m = fmaxf(m, __shfl_xor_sync(0xffffffffu, m, o));
        float e = (j < CC) ? expf(x - m) : 0.f;
        float ssum = e;
        #pragma unroll
        for (int o = 16; o > 0; o >>= 1) ssum += __shfl_xor_sync(0xffffffffu, ssum, o);
        float tt = 0.f;
        if (j < CC) {
            float pr = e * (1.f / ssum);
            tt = (j == c) ? fmaxf(logf(pr), -100.f) : fmaxf(log1pf(-pr), -100.f);
        }
        #pragma unroll
        for (int o = 16; o > 0; o >>= 1) tt += __shfl_xor_sync(0xffffffffu, tt, o);
        if (lane == 0) s_term[c] = -tt * (1.f / (float)CC);
    }
    __syncthreads();

    // ---- T1: accumulate batch-0 losses; compose fc1 norms ----
    if (tid < CC) {
        int j = tid;
        float ss = s_q[j]
            ? 0.9025f*s_n[2][j] + 0.095f*s_G[j*41 + j] + 0.0025f*s_n[0][j]
            : s_n[2][j];
        s_invc1[j] = 1.f / fmaxf(sqrtf(ss), 1e-12f);
    }
    if (tid == 0) {
        float tot = 0.f;
        for (int c = 0; c < CC; c++) tot += s_rowsum[c];
        s_acc[0] -= tot * (1.f / (float)(CC*CC));
        float ls = 0.f; int n = 0;
        for (int c = 0; c < CC; c++) if (s_q[c]) { ls += s_term[c]; n++; }
        s_acc[1] += ls;
        if (n > 0) s_acc[1] /= (float)n;      // divides ACCUMULATED value, per reference
    }
    __syncthreads();

    // ---- T2: batch-1 epilogue with EMA-composed cos dots ----
    for (int c = wid; c < CC; c += 8) {
        int j = lane;
        bool pres = __ldg(&label[CC + c]) > 0.5f;
        float v = 1e-5f;
        if (j < CC) {
            float m1 = s_G[j*41 + 20 + c];
            float raw = s_q[j] ? fmaf(0.95f, m1, 0.05f * s_G[(20+j)*41 + 20 + c]) : m1;
            v = fabsf(raw * s_invf1[c] * s_invc1[j]);
            v = fminf(fmaxf(v, 1e-5f), 1.f - 1e-5f);
        }
        float lt = 0.f, ov = -1e30f;
        if (j < CC) {
            lt = (j == c) ? (pres ? logf(v) : log1pf(-v)) : log1pf(-v);
            ov = (j == c) ? -1e30f : v;
        }
        float rs = lt, om = ov;
        #pragma unroll
        for (int o = 16; o > 0; o >>= 1) {
            rs += __shfl_xor_sync(0xffffffffu, rs, o);
            om  = fmaxf(om, __shfl_xor_sync(0xffffffffu, om, o));
        }
        if (lane == 0) { s_rowsum[c] = rs; s_q1[c] = (pres && om < 0.6f) ? 1 : 0; }

        float x = (j < CC) ? s_G[(40+j)*41 + 20 + c] : -3.4e38f;
        float m = x;
        #pragma unroll
        for (int o = 16; o > 0; o >>= 1) m = fmaxf(m, __shfl_xor_sync(0xffffffffu, m, o));
        float e = (j < CC) ? expf(x - m) : 0.f;
        float ssum = e;
        #pragma unroll
        for (int o = 16; o > 0; o >>= 1) ssum += __shfl_xor_sync(0xffffffffu, ssum, o);
        float tt = 0.f;
        if (j < CC) {
            float pr = e * (1.f / ssum);
            tt = (j == c) ? fmaxf(logf(pr), -100.f) : fmaxf(log1pf(-pr), -100.f);
        }
        #pragma unroll
        for (int o = 16; o > 0; o >>= 1) tt += __shfl_xor_sync(0xffffffffu, tt, o);
        if (lane == 0) s_term[c] = -tt * (1.f / (float)CC);
    }
    __syncthreads();

    if (tid == 0) {
        float tot = 0.f;
        for (int c = 0; c < CC; c++) tot += s_rowsum[c];
        s_acc[0] -= tot * (1.f / (float)(CC*CC));
        float ls = 0.f; int n = 0;
        for (int c = 0; c < CC; c++) if (s_q1[c]) { ls += s_term[c]; n++; }
        s_acc[1] += ls;
        if (n > 0) s_acc[1] /= (float)n;
        out[0] = s_acc[0] + s_acc[1];
    }

    // ---- tail cleanup: g_fsm + counters ----
    {
        float4 z4 = make_float4(0.f, 0.f, 0.f, 0.f);
        float4* f4 = (float4*)g_fsm;
        for (int i = tid; i < (BB*CC*DD)/4; i += 256) f4[i] = z4;
        if (tid == 0) { g_sync1 = 0; g_sync2 = 0; }
    }
}

extern "C" void kernel_launch(void* const* d_in, const int* in_sizes, int n_in,
                              void* d_out, int out_size)
{
    (void)in_sizes; (void)n_in; (void)out_size;
    const float* fmap  = (const float*)d_in[0];
    const float* cam   = (const float*)d_in[1];
    const float* label = (const float*)d_in[2];
    const float* proj  = (const float*)d_in[3];
    const float* fc0   = (const float*)d_in[4];
    const float* hig   = (const float*)d_in[5];
    const float* low   = (const float*)d_in[6];
    const float* bg    = (const float*)d_in[7];
    float* out = (float*)d_out;

    k_pseudo <<<BB*196, 256>>>(cam, label, hig, low, bg);
    k_main   <<<60, 256>>>(fmap, label, fc0, proj, out);
}

// round 15
// speedup vs baseline: 1.3940x; 1.3940x over previous
#include <cuda_runtime.h>

#define BB 2
#define CC 20
#define DD 256
#define WW 448
#define HWp 200704      // 448*448
#define FH 28
#define FW 28
#define FHW 784
#define KTOP 25

// ---- scratch (device globals). Invariant: zero at launch entry, re-zeroed by
// the k_loss2 fan-in epilogue before launch exit. g_Wt/g_G/g_nrm are
// overwrite-before-read every launch and need no zero invariant.
static __device__ float g_W   [BB*CC*FHW];
static __device__ float g_Wt  [BB*CC*FHW];
static __device__ int   g_cnt [BB*CC];
static __device__ int   g_wtflag;        // g_Wt-ready flag (producer block in k_fsm)
static __device__ int   g_sync;          // fan-in counter for k_loss2
static __device__ float g_fsm [BB*CC*DD];
static __device__ float g_G   [60*40];   // G[t][s]: t in {fc0(0-19), f0(20-39), proj(40-59)}, s in {f0(0-19), f1(20-39)}
static __device__ float g_nrm [3*CC];    // sumsq rows: 0:f0, 1:f1, 2:fc0

// ---- pseudo-label + bilinear-weight scatter (fmax-only top-2 + rare rescan) ----
__global__ __launch_bounds__(256) void k_pseudo(
    const float* __restrict__ cam, const float* __restrict__ label,
    const float* __restrict__ hig, const float* __restrict__ low,
    const float* __restrict__ bg)
{
    __shared__ int   s_np;
    __shared__ int   s_list[CC];
    __shared__ float s_W[CC*3*30];   // [c][row 0..2][col 0..29] unclamped tile
    __shared__ int   s_cnt[CC];

    int tid = threadIdx.x;
    int b    = blockIdx.x / 196;
    int pblk = blockIdx.x % 196;
    int P0   = pblk * 1024;
    int p    = P0 + tid * 4;

    for (int i = tid; i < CC*90; i += 256) s_W[i] = 0.f;
    if (tid < CC) s_cnt[tid] = 0;
    if (tid < 32) {
        float lv = (tid < CC) ? __ldg(&label[b*CC + tid]) : 0.f;
        unsigned m = __ballot_sync(0xffffffffu, lv > 0.5f);
        if (tid < CC && lv > 0.5f) {
            int pos = __popc(m & ((1u << tid) - 1u));
            s_list[pos] = tid;
        }
        if (tid == 0) s_np = __popc(m);
    }
    __syncthreads();

    int np = s_np;
    const float* base = cam + (size_t)b * CC * HWp;

    float t1[4], t2[4];
    #pragma unroll
    for (int e = 0; e < 4; e++) { t1[e] = -1e30f; t2[e] = -1e30f; }

    for (int k = 0; k < np; k++) {
        int c = s_list[k];
        float4 v = __ldg((const float4*)(base + (size_t)c * HWp + p));
        float tm;
        tm = fminf(t1[0], v.x); t2[0] = fmaxf(t2[0], tm); t1[0] = fmaxf(t1[0], v.x);
        tm = fminf(t1[1], v.y); t2[1] = fmaxf(t2[1], tm); t1[1] = fmaxf(t1[1], v.y);
        tm = fminf(t1[2], v.z); t2[2] = fmaxf(t2[2], tm); t1[2] = fmaxf(t1[2], v.z);
        tm = fminf(t1[3], v.w); t2[3] = fmaxf(t2[3], tm); t1[3] = fmaxf(t1[3], v.w);
    }
    float Hh = __ldg(hig), Ll = __ldg(low), Gg = __ldg(bg);

    int Y0 = P0 / WW;
    int r0 = (int)floorf(((float)Y0 + 0.5f) * 0.0625f - 0.5f);

    #pragma unroll
    for (int e = 0; e < 4; e++) {
        float a = t1[e], s = t2[e];
        if (np < CC) { a = fmaxf(a, 0.f); s = fmaxf(s, 0.f); }  // absent classes are zeros
        bool lab = !(a < Hh) && !(a < Ll) && !(a < Gg) && !((a - s < 0.3f) && (a > Hh));
        lab = lab && (np > 0);
        if (lab) {
            int c = s_list[0];
            if (np > 1) {
                int pp0 = p + e;
                for (int k = 0; k < np; k++) {
                    int cc2 = s_list[k];
                    if (__ldg(&base[(size_t)cc2 * HWp + pp0]) == a) { c = cc2; break; }
                }
            }
            atomicAdd(&s_cnt[c], 1);
            int pp = p + e;
            int y = pp / WW, x = pp - y * WW;
            float sy = ((float)y + 0.5f) * 0.0625f - 0.5f;   // exact (dyadic)
            float sx = ((float)x + 0.5f) * 0.0625f - 0.5f;
            float y0f = floorf(sy), x0f = floorf(sx);
            float fy = sy - y0f,   fx = sx - x0f;
            int rr  = (int)y0f - r0;        // 0..1 (taps rr, rr+1 in [0,2])
            int c0  = (int)x0f + 1;         // 0..28
            float* tp = &s_W[c*90 + rr*30 + c0];
            atomicAdd(&tp[0],  (1.f-fy)*(1.f-fx));
            atomicAdd(&tp[1],  (1.f-fy)*fx);
            atomicAdd(&tp[30], fy*(1.f-fx));
            atomicAdd(&tp[31], fy*fx);
        }
    }
    __syncthreads();

    if (tid < CC && s_cnt[tid] > 0) atomicAdd(&g_cnt[b*CC + tid], s_cnt[tid]);
    for (int i = tid; i < CC*90; i += 256) {
        float v = s_W[i];
        if (v != 0.f) {
            int c = i / 90, rem = i - c*90;
            int rr = rem / 30, col = rem - rr*30;
            int gy = min(max(r0 + rr, 0), FH-1);
            int gx = min(max(col - 1, 0), FW-1);
            atomicAdd(&g_W[(b*CC + c)*FHW + gy*FW + gx], v);
        }
    }
}

// ---- fsm: grid = BB*28rows*2halves + 1 producer = 113 blocks, 128 thr.
//      Block 112 builds g_Wt for rare present&&cnt==0 classes, then raises
//      g_wtflag; consumer blocks spin on the flag ONLY if they need g_Wt
//      (never, in the common case). Deadlock-free: 113 blocks co-resident. ----
__global__ __launch_bounds__(128) void k_fsm(
    const float* __restrict__ fmap, const float* __restrict__ cam,
    const float* __restrict__ label)
{
    int tid = threadIdx.x, wid = tid >> 5, lane = tid & 31;

    if (blockIdx.x == BB*FH*2) {
        // ---- producer: top-25 fallback for present && cnt==0 classes ----
        __shared__ float s_wv[4];
        __shared__ int   s_wi[4];
        __shared__ int   s_bi;
        __shared__ int   s_top[KTOP];
        __shared__ float s_wt[FHW];

        for (int bc = 0; bc < BB*CC; bc++) {
            if (__ldg(&label[bc]) <= 0.5f) continue;
            if (g_cnt[bc] != 0) continue;

            const float4* cp = (const float4*)(cam + (size_t)bc * HWp);
            float vals[KTOP]; int idxs[KTOP];   // ascending: vals[24]=max
            #pragma unroll
            for (int k = 0; k < KTOP; k++) { vals[k] = -1e30f; idxs[k] = 0x7fffffff; }
            float vmin = -1e30f;
            for (int j = tid; j < HWp/4; j += 128) {
                float4 v = __ldg(&cp[j]);
                int pbase = j * 4;
                float vv[4] = { v.x, v.y, v.z, v.w };
                #pragma unroll
                for (int e = 0; e < 4; e++) {
                    float x = vv[e];
                    if (x > vmin) {
                        int k = 0;
                        while (k < KTOP-1 && x > vals[k+1]) { vals[k] = vals[k+1]; idxs[k] = idxs[k+1]; k++; }
                        vals[k] = x; idxs[k] = pbase + e;
                        vmin = vals[0];
                    }
                }
            }
            int ptr = KTOP - 1;
            for (int r = 0; r < KTOP; r++) {
                float v  = (ptr >= 0) ? vals[ptr] : -1e30f;
                int   ii = (ptr >= 0) ? idxs[ptr] : 0x7fffffff;
                float mv = v; int mi = ii;
                #pragma unroll
                for (int off = 16; off > 0; off >>= 1) {
                    float ov = __shfl_down_sync(0xffffffffu, mv, off);
                    int   oi = __shfl_down_sync(0xffffffffu, mi, off);
                    if (ov > mv || (ov == mv && oi < mi)) { mv = ov; mi = oi; }
                }
                if (lane == 0) { s_wv[wid] = mv; s_wi[wid] = mi; }
                __syncthreads();
                if (tid == 0) {
                    float bv = s_wv[0]; int bi = s_wi[0];
                    #pragma unroll
                    for (int w = 1; w < 4; w++) {
                        if (s_wv[w] > bv || (s_wv[w] == bv && s_wi[w] < bi)) { bv = s_wv[w]; bi = s_wi[w]; }
                    }
                    s_bi = bi;
                    s_top[r] = bi;
                }
                __syncthreads();
                if (ptr >= 0 && idxs[ptr] == s_bi) ptr--;
            }
            for (int i = tid; i < FHW; i += 128) s_wt[i] = 0.f;
            __syncthreads();
            if (tid == 0) {
                for (int r = 0; r < KTOP; r++) {
                    int pp = s_top[r];
                    int y = pp / WW, x = pp - y * WW;
                    float sy = ((float)y + 0.5f) * 0.0625f - 0.5f;
                    float sx = ((float)x + 0.5f) * 0.0625f - 0.5f;
                    float y0f = floorf(sy), x0f = floorf(sx);
                    float fy = sy - y0f,   fx = sx - x0f;
                    int y0 = (int)y0f, x0 = (int)x0f;
                    int ya = min(max(y0, 0), FH-1),   yb = min(max(y0+1, 0), FH-1);
                    int xa = min(max(x0, 0), FW-1),   xb = min(max(x0+1, 0), FW-1);
                    s_wt[ya*FW + xa] += (1.f-fy)*(1.f-fx);
                    s_wt[ya*FW + xb] += (1.f-fy)*fx;
                    s_wt[yb*FW + xa] += fy*(1.f-fx);
                    s_wt[yb*FW + xb] += fy*fx;
                }
            }
            __syncthreads();
            for (int i = tid; i < FHW; i += 128) g_Wt[bc*FHW + i] = s_wt[i];
            __syncthreads();
        }
        __threadfence();
        if (tid == 0) atomicExch(&g_wtflag, 1);
        return;
    }

    // ---- consumers: R12 fsm row-task ----
    __shared__ int    s_np, s_nact, s_need;
    __shared__ int    s_list[CC];
    __shared__ int    s_act[CC];
    __shared__ int    s_nz[CC];
    __shared__ int    s_cnti[CC];
    __shared__ float  s_inv[CC];
    __shared__ float4 s_cw[CC][7];

    int half = blockIdx.x & 1;
    int row  = (blockIdx.x >> 1) % FH;
    int b    = blockIdx.x / (2*FH);

    int d = half*128 + tid;
    const float4* fr = (const float4*)(fmap + ((size_t)(b*DD + d)) * FHW + row*FW);
    float4 f[7];
    #pragma unroll
    for (int i = 0; i < 7; i++) f[i] = __ldg(&fr[i]);

    if (tid < 32) {
        float lv = (tid < CC) ? __ldg(&label[b*CC + tid]) : 0.f;
        unsigned m = __ballot_sync(0xffffffffu, lv > 0.5f);
        if (tid < CC && lv > 0.5f) s_list[__popc(m & ((1u << tid) - 1u))] = tid;
        if (tid == 0) { s_np = __popc(m); s_need = 0; }
    }
    if (tid < CC) s_nz[tid] = 0;
    __syncthreads();
    int np = s_np;

    if (tid < np) {
        int bc = b*CC + s_list[tid];
        int cnt = g_cnt[bc];
        s_cnti[tid] = cnt;
        s_inv[tid]  = (cnt > 0) ? (1.f / (float)cnt) : 0.04f;
        if (cnt == 0) s_need = 1;
    }
    __syncthreads();

    if (s_need) {   // rare: wait for producer's g_Wt (producer is co-resident)
        if (tid == 0) { while (atomicAdd(&g_wtflag, 0) == 0) __nanosleep(128); }
        __syncthreads();
        __threadfence();
    }

    for (int idx = tid; idx < np*7; idx += 128) {
        int k = idx / 7, q = idx - k*7;
        int bc = b*CC + s_list[k];
        const float4* src = (s_cnti[k] > 0)
            ? (const float4*)(g_W  + bc*FHW + row*FW)
            : (const float4*)(g_Wt + bc*FHW + row*FW);
        float4 v = __ldcg(&src[q]);
        float inv = s_inv[k];
        v.x *= inv; v.y *= inv; v.z *= inv; v.w *= inv;
        s_cw[k][q] = v;
        if (v.x != 0.f || v.y != 0.f || v.z != 0.f || v.w != 0.f) s_nz[k] = 1;
    }
    __syncthreads();

    if (tid < 32) {
        bool a = (tid < np) && s_nz[tid];
        unsigned m = __ballot_sync(0xffffffffu, a);
        if (a) s_act[__popc(m & ((1u << tid) - 1u))] = tid;
        if (tid == 0) s_nact = __popc(m);
    }
    __syncthreads();
    int nact = s_nact;
    if (nact == 0) return;

    for (int a = 0; a < nact; a++) {
        int k = s_act[a];
        int c = s_list[k];
        float a0 = 0.f, a1 = 0.f, a2 = 0.f, a3 = 0.f;
        #pragma unroll
        for (int i = 0; i < 7; i++) {
            float4 w = s_cw[k][i];
            a0 = fmaf(f[i].x, w.x, a0);
            a1 = fmaf(f[i].y, w.y, a1);
            a2 = fmaf(f[i].z, w.z, a2);
            a3 = fmaf(f[i].w, w.w, a3);
        }
        atomicAdd(&g_fsm[(b*CC + c)*DD + d], (a0 + a1) + (a2 + a3));
    }
}

// ---- fused loss: grid 60 x 640. Each block: 40 G-dots (20 warps x 2 sources)
//      + folded norm (wid==0). Last-arriving block runs the scalar epilogue +
//      scratch cleanup (fan-in, deadlock-free). ----
// G mapping (t-major, stride 41 in shared): M0[c][j]=G[j][c]  M1[c][j]=G[j][20+c]
// M2[c][j]=G[20+j][20+c]  M3[c][j]=G[40+j][c]  M4[c][j]=G[40+j][20+c]
__global__ __launch_bounds__(640) void k_loss2(
    const float* __restrict__ label, const float* __restrict__ fc0,
    const float* __restrict__ proj, float* __restrict__ out)
{
    int t = blockIdx.x;
    int tid = threadIdx.x, wid = tid >> 5, lane = tid & 31;

    {
        int type = t / 20, row = t % 20;
        const float* tp = (type == 0) ? (fc0 + row*DD)
                        : (type == 1) ? (g_fsm + row*DD)
                                      : (proj + row*DD);
        const float4* t4 = (const float4*)tp;
        float4 ta = __ldg(&t4[lane*2]);
        float4 tb = __ldg(&t4[lane*2 + 1]);
        #pragma unroll
        for (int i = 0; i < 2; i++) {
            int s = wid*2 + i;
            const float4* s4 = (const float4*)(g_fsm + s*DD);
            float4 sa = __ldg(&s4[lane*2]);
            float4 sb = __ldg(&s4[lane*2 + 1]);
            float d = sa.x*ta.x + sa.y*ta.y + sa.z*ta.z + sa.w*ta.w
                    + sb.x*tb.x + sb.y*tb.y + sb.z*tb.z + sb.w*tb.w;
            #pragma unroll
            for (int o = 16; o > 0; o >>= 1) d += __shfl_xor_sync(0xffffffffu, d, o);
            if (lane == 0) g_G[t*40 + s] = d;
        }
        // folded norms: type0 -> fc0 row (slot 40+row); type1 -> f0 row (slot row);
        //               type2 -> f1 row (slot 20+row, extra load)
        if (wid == 0) {
            float4 ua = ta, ub = tb;
            int slot;
            if (type == 0)      slot = 40 + row;
            else if (type == 1) slot = row;
            else {
                const float4* r4 = (const float4*)(g_fsm + (CC + row)*DD);
                ua = __ldg(&r4[lane*2]);
                ub = __ldg(&r4[lane*2 + 1]);
                slot = 20 + row;
            }
            float ss = ua.x*ua.x + ua.y*ua.y + ua.z*ua.z + ua.w*ua.w
                     + ub.x*ub.x + ub.y*ub.y + ub.z*ub.z + ub.w*ub.w;
            #pragma unroll
            for (int o = 16; o > 0; o >>= 1) ss += __shfl_xor_sync(0xffffffffu, ss, o);
            if (lane == 0) g_nrm[slot] = ss;
        }
    }

    // ---- fan-in: last block to arrive runs the epilogue ----
    __threadfence();
    __shared__ int s_last;
    if (tid == 0) s_last = (atomicAdd(&g_sync, 1) == 59) ? 1 : 0;
    __syncthreads();
    if (!s_last) return;
    __threadfence();

    __shared__ float s_G[60*41];
    __shared__ float s_n[3][CC];
    __shared__ float s_invf0[CC], s_invf1[CC], s_invc0[CC], s_invc1[CC];
    __shared__ float s_rowsum[CC], s_term[CC];
    __shared__ int   s_q[CC], s_q1[CC];
    __shared__ float s_acc[2];

    for (int i = tid; i < 60*40; i += 640) {
        int tt2 = i / 40, s = i - tt2*40;
        s_G[tt2*41 + s] = __ldcg(&g_G[i]);
    }
    if (tid < 60) s_n[tid/CC][tid%CC] = __ldcg(&g_nrm[tid]);
    if (tid == 0) { s_acc[0] = 0.f; s_acc[1] = 0.f; }
    __syncthreads();

    if (tid < CC) {
        s_invf0[tid] = 1.f / fmaxf(sqrtf(s_n[0][tid]), 1e-12f);
        s_invf1[tid] = 1.f / fmaxf(sqrtf(s_n[1][tid]), 1e-12f);
        s_invc0[tid] = 1.f / fmaxf(sqrtf(s_n[2][tid]), 1e-12f);
    }
    __syncthreads();

    // ---- T0: batch-0 epilogue (warp c, lane j) ----
    if (wid < CC) {
        int c = wid, j = lane;
        bool pres = __ldg(&label[c]) > 0.5f;
        float v = 1e-5f;
        if (j < CC) {
            v = fabsf(s_G[j*41 + c] * s_invf0[c] * s_invc0[j]);
            v = fminf(fmaxf(v, 1e-5f), 1.f - 1e-5f);
        }
        float lt = 0.f, ov = -1e30f;
        if (j < CC) {
            lt = (j == c) ? (pres ? logf(v) : log1pf(-v)) : log1pf(-v);
            ov = (j == c) ? -1e30f : v;
        }
        float rs = lt, om = ov;
        #pragma unroll
        for (int o = 16; o > 0; o >>= 1) {
            rs += __shfl_xor_sync(0xffffffffu, rs, o);
            om  = fmaxf(om, __shfl_xor_sync(0xffffffffu, om, o));
        }
        if (lane == 0) { s_rowsum[c] = rs; s_q[c] = (pres && om < 0.6f) ? 1 : 0; }

        float x = (j < CC) ? s_G[(40+j)*41 + c] : -3.4e38f;
        float m = x;
        #pragma unroll
        for (int o = 16; o > 0; o >>= 1) m = fmaxf(m, __shfl_xor_sync(0xffffffffu, m, o));
        float e = (j < CC) ? expf(x - m) : 0.f;
        float ssum = e;
        #pragma unroll
        for (int o = 16; o > 0; o >>= 1) ssum += __shfl_xor_sync(0xffffffffu, ssum, o);
        float tt = 0.f;
        if (j < CC) {
            float pr = e * (1.f / ssum);
            tt = (j == c) ? fmaxf(logf(pr), -100.f) : fmaxf(log1pf(-pr), -100.f);
        }
        #pragma unroll
        for (int o = 16; o > 0; o >>= 1) tt += __shfl_xor_sync(0xffffffffu, tt, o);
        if (lane == 0) s_term[c] = -tt * (1.f / (float)CC);
    }
    __syncthreads();

    // ---- T1: accumulate batch-0 losses; compose fc1 norms ----
    if (tid < CC) {
        int j = tid;
        float ss = s_q[j]
            ? 0.9025f*s_n[2][j] + 0.095f*s_G[j*41 + j] + 0.0025f*s_n[0][j]
            : s_n[2][j];
        s_invc1[j] = 1.f / fmaxf(sqrtf(ss), 1e-12f);
    }
    if (tid == 0) {
        float tot = 0.f;
        for (int c = 0; c < CC; c++) tot += s_rowsum[c];
        s_acc[0] -= tot * (1.f / (float)(CC*CC));
        float ls = 0.f; int n = 0;
        for (int c = 0; c < CC; c++) if (s_q[c]) { ls += s_term[c]; n++; }
        s_acc[1] += ls;
        if (n > 0) s_acc[1] /= (float)n;      // divides ACCUMULATED value, per reference
    }
    __syncthreads();

    // ---- T2: batch-1 epilogue with EMA-composed cos dots ----
    if (wid < CC) {
        int c = wid, j = lane;
        bool pres = __ldg(&label[CC + c]) > 0.5f;
        float v = 1e-5f;
        if (j < CC) {
            float m1 = s_G[j*41 + 20 + c];
            float raw = s_q[j] ? fmaf(0.95f, m1, 0.05f * s_G[(20+j)*41 + 20 + c]) : m1;
            v = fabsf(raw * s_invf1[c] * s_invc1[j]);
            v = fminf(fmaxf(v, 1e-5f), 1.f - 1e-5f);
        }
        float lt = 0.f, ov = -1e30f;
        if (j < CC) {
            lt = (j == c) ? (pres ? logf(v) : log1pf(-v)) : log1pf(-v);
            ov = (j == c) ? -1e30f : v;
        }
        float rs = lt, om = ov;
        #pragma unroll
        for (int o = 16; o > 0; o >>= 1) {
            rs += __shfl_xor_sync(0xffffffffu, rs, o);
            om  = fmaxf(om, __shfl_xor_sync(0xffffffffu, om, o));
        }
        if (lane == 0) { s_rowsum[c] = rs; s_q1[c] = (pres && om < 0.6f) ? 1 : 0; }

        float x = (j < CC) ? s_G[(40+j)*41 + 20 + c] : -3.4e38f;
        float m = x;
        #pragma unroll
        for (int o = 16; o > 0; o >>= 1) m = fmaxf(m, __shfl_xor_sync(0xffffffffu, m, o));
        float e = (j < CC) ? expf(x - m) : 0.f;
        float ssum = e;
        #pragma unroll
        for (int o = 16; o > 0; o >>= 1) ssum += __shfl_xor_sync(0xffffffffu, ssum, o);
        float tt = 0.f;
        if (j < CC) {
            float pr = e * (1.f / ssum);
            tt = (j == c) ? fmaxf(logf(pr), -100.f) : fmaxf(log1pf(-pr), -100.f);
        }
        #pragma unroll
        for (int o = 16; o > 0; o >>= 1) tt += __shfl_xor_sync(0xffffffffu, tt, o);
        if (lane == 0) s_term[c] = -tt * (1.f / (float)CC);
    }
    __syncthreads();

    if (tid == 0) {
        float tot = 0.f;
        for (int c = 0; c < CC; c++) tot += s_rowsum[c];
        s_acc[0] -= tot * (1.f / (float)(CC*CC));
        float ls = 0.f; int n = 0;
        for (int c = 0; c < CC; c++) if (s_q1[c]) { ls += s_term[c]; n++; }
        s_acc[1] += ls;
        if (n > 0) s_acc[1] /= (float)n;
        out[0] = s_acc[0] + s_acc[1];
    }

    // ---- cleanup: restore zero-scratch invariant for next launch ----
    {
        float4 z4 = make_float4(0.f, 0.f, 0.f, 0.f);
        float4* w4 = (float4*)g_W;
        for (int i = tid; i < (BB*CC*FHW)/4; i += 640) w4[i] = z4;
        float4* f4 = (float4*)g_fsm;
        for (int i = tid; i < (BB*CC*DD)/4; i += 640) f4[i] = z4;
        if (tid < BB*CC) g_cnt[tid] = 0;
        if (tid == 0) { g_sync = 0; g_wtflag = 0; }
    }
}

extern "C" void kernel_launch(void* const* d_in, const int* in_sizes, int n_in,
                              void* d_out, int out_size)
{
    (void)in_sizes; (void)n_in; (void)out_size;
    const float* fmap  = (const float*)d_in[0];
    const float* cam   = (const float*)d_in[1];
    const float* label = (const float*)d_in[2];
    const float* proj  = (const float*)d_in[3];
    const float* fc0   = (const float*)d_in[4];
    const float* hig   = (const float*)d_in[5];
    const float* low   = (const float*)d_in[6];
    const float* bg    = (const float*)d_in[7];
    float* out = (float*)d_out;

    k_pseudo <<<BB*196, 256>>>(cam, label, hig, low, bg);
    k_fsm    <<<BB*FH*2 + 1, 128>>>(fmap, cam, label);
    k_loss2  <<<60, 640>>>(label, fc0, proj, out);
}